// round 2
// baseline (speedup 1.0000x reference)
#include <cuda_runtime.h>

#define BB 16
#define LL 2048
#define HH 768
#define DD 64
#define VV 30000

// Scratch (device globals — no allocation allowed in kernel_launch)
__device__ float g_E[(size_t)BB * LL * DD];                // gathered embeddings  (8 MB)
__device__ float g_F[(size_t)BB * LL * DD];                // E @ w                (8 MB)
__device__ float g_A[(size_t)BB * LL * LL];                // weighted scores    (256 MB)

// ---------------------------------------------------------------------------
// Kernel 0: E[b,l,:] = ae[x[b,l],:];  F = E @ w   (w cached in smem)
// 256 threads handle 4 rows (64 threads per row).
// Token buffer dtype (int32 vs int64) is sniffed in-kernel: if any of the
// first 32 odd 32-bit words is nonzero, layout is int32. Tokens clamped.
// ---------------------------------------------------------------------------
__global__ void __launch_bounds__(256) k_gather(const float* __restrict__ ae,
                                                const void* __restrict__ xraw,
                                                const float* __restrict__ w) {
    __shared__ float ws[64 * 64];
    __shared__ float es[4][64];
    for (int t = threadIdx.x; t < 64 * 64; t += 256) ws[t] = w[t];

    // dtype sniff (uniform across all threads; reads are in-bounds for both
    // layouts: 64 ints = 256B <= min buffer size of 128KB)
    const int* xi = (const int*)xraw;
    bool is64 = true;
#pragma unroll
    for (int k = 0; k < 32; k++)
        if (xi[2 * k + 1] != 0) is64 = false;

    int sub = threadIdx.x >> 6;
    int d   = threadIdx.x & 63;
    int row = blockIdx.x * 4 + sub;

    long long tok;
    if (is64) tok = ((const long long*)xraw)[row];
    else      tok = (long long)xi[row];
    if (tok < 0) tok = 0;
    if (tok >= VV) tok = VV - 1;

    float e = ae[(size_t)tok * 64 + d];
    es[sub][d] = e;
    g_E[(size_t)row * 64 + d] = e;
    __syncthreads();
    float f = 0.f;
#pragma unroll
    for (int k = 0; k < 64; k++) f += es[sub][k] * ws[k * 64 + d];
    g_F[(size_t)row * 64 + d] = f;
}

// ---------------------------------------------------------------------------
// Kernel 1: A[b,i,j] = (F[b,i] . E[b,j]) * (i+1)/(j+1) for i<j else 0
// 128x128 tile, K=64 split into two 32-deep smem passes.
// Only tiles with iT <= jT are computed (others never read by pass 2).
// ---------------------------------------------------------------------------
__global__ void __launch_bounds__(256) k_scores() {
    int jT = blockIdx.x, iT = blockIdx.y, b = blockIdx.z;
    if (iT > jT) return;

    __shared__ float Fs[32][132];
    __shared__ float Es[32][132];

    int iBase = iT * 128, jBase = jT * 128;
    const float* Fg = g_F + ((size_t)b * LL + iBase) * 64;
    const float* Eg = g_E + ((size_t)b * LL + jBase) * 64;

    int tx = threadIdx.x & 15, ty = threadIdx.x >> 4;
    int i0 = ty * 8, j0 = tx * 8;

    float acc[8][8];
#pragma unroll
    for (int r = 0; r < 8; r++)
#pragma unroll
        for (int c = 0; c < 8; c++) acc[r][c] = 0.f;

    for (int kp = 0; kp < 2; kp++) {
        for (int t = threadIdx.x; t < 128 * 32; t += 256) {
            int r = t >> 5, k = t & 31;
            Fs[k][r] = Fg[(size_t)r * 64 + kp * 32 + k];
            Es[k][r] = Eg[(size_t)r * 64 + kp * 32 + k];
        }
        __syncthreads();
#pragma unroll
        for (int k = 0; k < 32; k++) {
            float4 a0 = *(const float4*)&Fs[k][i0];
            float4 a1 = *(const float4*)&Fs[k][i0 + 4];
            float4 b0 = *(const float4*)&Es[k][j0];
            float4 b1 = *(const float4*)&Es[k][j0 + 4];
            float av[8] = {a0.x, a0.y, a0.z, a0.w, a1.x, a1.y, a1.z, a1.w};
            float bv[8] = {b0.x, b0.y, b0.z, b0.w, b1.x, b1.y, b1.z, b1.w};
#pragma unroll
            for (int r = 0; r < 8; r++)
#pragma unroll
                for (int c = 0; c < 8; c++) acc[r][c] += av[r] * bv[c];
        }
        __syncthreads();
    }

    float* Ap = g_A + (size_t)b * LL * LL;
    float rj[8];
#pragma unroll
    for (int c = 0; c < 8; c++) rj[c] = 1.0f / (float)(jBase + j0 + c + 1);
#pragma unroll
    for (int r = 0; r < 8; r++) {
        int gi = iBase + i0 + r;
        float wi = (float)(gi + 1);
        float o[8];
#pragma unroll
        for (int c = 0; c < 8; c++) {
            int gj = jBase + j0 + c;
            o[c] = (gi < gj) ? acc[r][c] * wi * rj[c] : 0.f;
        }
        float4* dst = (float4*)&Ap[(size_t)gi * LL + jBase + j0];
        dst[0] = make_float4(o[0], o[1], o[2], o[3]);
        dst[1] = make_float4(o[4], o[5], o[6], o[7]);
    }
}

// ---------------------------------------------------------------------------
// Kernel 2: res[b,j,h] = bert_x[b,j,h] + sum_i A[b,i,j] * bert_x[b,i,h]
// 128(j) x 128(h) output tile per CTA, K(i) chunks of 32, causal K-range.
// ---------------------------------------------------------------------------
__global__ void __launch_bounds__(256, 2) k_apply(const float* __restrict__ bx,
                                                  float* __restrict__ out) {
    int hT = blockIdx.x, jT = blockIdx.y, b = blockIdx.z;

    __shared__ float As[32][132];
    __shared__ float Xs[32][132];

    int jBase = jT * 128, hBase = hT * 128;
    const float* Ap = g_A + (size_t)b * LL * LL;
    const float* Xb = bx + (size_t)b * LL * HH;

    int tx = threadIdx.x & 15, ty = threadIdx.x >> 4;

    float acc[8][8];
#pragma unroll
    for (int r = 0; r < 8; r++)
#pragma unroll
        for (int c = 0; c < 8; c++) acc[r][c] = 0.f;

    int nChunks = (jT + 1) * 4;  // i only runs up to the diagonal tile
    for (int ck = 0; ck < nChunks; ck++) {
        int i0 = ck * 32;
        for (int t = threadIdx.x; t < 1024; t += 256) {
            int row = t >> 5, c4 = t & 31;
            *(float4*)&As[row][c4 * 4] =
                *(const float4*)&Ap[(size_t)(i0 + row) * LL + jBase + c4 * 4];
            *(float4*)&Xs[row][c4 * 4] =
                *(const float4*)&Xb[(size_t)(i0 + row) * HH + hBase + c4 * 4];
        }
        __syncthreads();
#pragma unroll
        for (int k = 0; k < 32; k++) {
            float4 a0 = *(const float4*)&As[k][ty * 8];
            float4 a1 = *(const float4*)&As[k][ty * 8 + 4];
            float4 x0 = *(const float4*)&Xs[k][tx * 8];
            float4 x1 = *(const float4*)&Xs[k][tx * 8 + 4];
            float av[8] = {a0.x, a0.y, a0.z, a0.w, a1.x, a1.y, a1.z, a1.w};
            float xv[8] = {x0.x, x0.y, x0.z, x0.w, x1.x, x1.y, x1.z, x1.w};
#pragma unroll
            for (int r = 0; r < 8; r++)
#pragma unroll
                for (int c = 0; c < 8; c++) acc[r][c] += av[r] * xv[c];
        }
        __syncthreads();
    }

#pragma unroll
    for (int r = 0; r < 8; r++) {
        int j = jBase + ty * 8 + r;
        size_t off = (size_t)j * HH + hBase + tx * 8;
        float4 b0 = *(const float4*)&Xb[off];
        float4 b1 = *(const float4*)&Xb[off + 4];
        float4 o0 = make_float4(b0.x + acc[r][0], b0.y + acc[r][1],
                                b0.z + acc[r][2], b0.w + acc[r][3]);
        float4 o1 = make_float4(b1.x + acc[r][4], b1.y + acc[r][5],
                                b1.z + acc[r][6], b1.w + acc[r][7]);
        float* ob = out + (size_t)b * LL * HH;
        *(float4*)&ob[off] = o0;
        *(float4*)&ob[off + 4] = o1;
    }
}

// ---------------------------------------------------------------------------
extern "C" void kernel_launch(void* const* d_in, const int* in_sizes, int n_in,
                              void* d_out, int out_size) {
    // Resolve inputs by element count (ordering-proof):
    //   bert_x: 16*2048*768 = 25165824
    //   x     : 16*2048     = 32768
    //   ae    : 30000*64    = 1920000
    //   w     : 64*64       = 4096
    const float* bert_x = nullptr;
    const void*  x      = nullptr;
    const float* ae     = nullptr;
    const float* w      = nullptr;
    for (int i = 0; i < n_in; i++) {
        switch (in_sizes[i]) {
            case 25165824: bert_x = (const float*)d_in[i]; break;
            case 32768:    x      = d_in[i];               break;
            case 1920000:  ae     = (const float*)d_in[i]; break;
            case 4096:     w      = (const float*)d_in[i]; break;
            default: break;
        }
    }
    float* out = (float*)d_out;

    k_gather<<<(BB * LL) / 4, 256>>>(ae, x, w);
    k_scores<<<dim3(LL / 128, LL / 128, BB), 256>>>();
    k_apply<<<dim3(HH / 128, LL / 128, BB), 256>>>(bert_x, out);
}

// round 4
// speedup vs baseline: 1.8744x; 1.8744x over previous
#include <cuda_runtime.h>
#include <cuda_bf16.h>
#include <cstdint>

#define BB 16
#define LL 2048
#define HH 768
#define DD 64
#define VV 30000

// ---------------------------------------------------------------------------
// Device-global scratch (no allocation allowed in kernel_launch)
// ---------------------------------------------------------------------------
__device__ float g_E[(size_t)BB * LL * DD];                    // 8 MB
__device__ float g_F[(size_t)BB * LL * DD];                    // 8 MB
__device__ __nv_bfloat16 g_Ah[(size_t)BB * LL * LL];           // scores^T hi [b][j][i]  128 MB
__device__ __nv_bfloat16 g_Al[(size_t)BB * LL * LL];           // scores^T lo            128 MB
__device__ __nv_bfloat16 g_Xh[(size_t)BB * HH * LL];           // bert_x^T hi [b][h][i]  50 MB
__device__ __nv_bfloat16 g_Xl[(size_t)BB * HH * LL];           // bert_x^T lo            50 MB

// ---------------------------------------------------------------------------
// Kernel 0: gather E = ae[x], F = E @ w
// ---------------------------------------------------------------------------
__global__ void __launch_bounds__(256) k_gather(const float* __restrict__ ae,
                                                const void* __restrict__ xraw,
                                                const float* __restrict__ w) {
    __shared__ float ws[64 * 64];
    __shared__ float es[4][64];
    for (int t = threadIdx.x; t < 64 * 64; t += 256) ws[t] = w[t];

    const int* xi = (const int*)xraw;
    bool is64 = true;
#pragma unroll
    for (int k = 0; k < 32; k++)
        if (xi[2 * k + 1] != 0) is64 = false;

    int sub = threadIdx.x >> 6;
    int d   = threadIdx.x & 63;
    int row = blockIdx.x * 4 + sub;

    long long tok;
    if (is64) tok = ((const long long*)xraw)[row];
    else      tok = (long long)xi[row];
    if (tok < 0) tok = 0;
    if (tok >= VV) tok = VV - 1;

    float e = ae[(size_t)tok * 64 + d];
    es[sub][d] = e;
    g_E[(size_t)row * 64 + d] = e;
    __syncthreads();
    float f = 0.f;
#pragma unroll
    for (int k = 0; k < 64; k++) f += es[sub][k] * ws[k * 64 + d];
    g_F[(size_t)row * 64 + d] = f;
}

// ---------------------------------------------------------------------------
// Kernel 1: scores (fp32 SIMT), epilogue writes TRANSPOSED bf16 hi/lo
//   A'[b][j][i] = (F[b,i].E[b,j]) * (i+1)/(j+1)  for i<j else 0
// ---------------------------------------------------------------------------
__global__ void __launch_bounds__(256) k_scores() {
    int jT = blockIdx.x, iT = blockIdx.y, b = blockIdx.z;
    if (iT > jT) return;

    __shared__ float Fs[32][132];
    __shared__ float Es[32][132];

    int iBase = iT * 128, jBase = jT * 128;
    const float* Fg = g_F + ((size_t)b * LL + iBase) * 64;
    const float* Eg = g_E + ((size_t)b * LL + jBase) * 64;

    int tx = threadIdx.x & 15, ty = threadIdx.x >> 4;
    int i0 = ty * 8, j0 = tx * 8;

    float acc[8][8];
#pragma unroll
    for (int r = 0; r < 8; r++)
#pragma unroll
        for (int c = 0; c < 8; c++) acc[r][c] = 0.f;

    for (int kp = 0; kp < 2; kp++) {
        for (int t = threadIdx.x; t < 128 * 32; t += 256) {
            int r = t >> 5, k = t & 31;
            Fs[k][r] = Fg[(size_t)r * 64 + kp * 32 + k];
            Es[k][r] = Eg[(size_t)r * 64 + kp * 32 + k];
        }
        __syncthreads();
#pragma unroll
        for (int k = 0; k < 32; k++) {
            float4 a0 = *(const float4*)&Fs[k][i0];
            float4 a1 = *(const float4*)&Fs[k][i0 + 4];
            float4 b0 = *(const float4*)&Es[k][j0];
            float4 b1 = *(const float4*)&Es[k][j0 + 4];
            float av[8] = {a0.x, a0.y, a0.z, a0.w, a1.x, a1.y, a1.z, a1.w};
            float bv[8] = {b0.x, b0.y, b0.z, b0.w, b1.x, b1.y, b1.z, b1.w};
#pragma unroll
            for (int r = 0; r < 8; r++)
#pragma unroll
                for (int c = 0; c < 8; c++) acc[r][c] += av[r] * bv[c];
        }
        __syncthreads();
    }

    __nv_bfloat16* Ah = g_Ah + (size_t)b * LL * LL;
    __nv_bfloat16* Al = g_Al + (size_t)b * LL * LL;
#pragma unroll
    for (int c = 0; c < 8; c++) {
        int gj = jBase + j0 + c;
        float rj = 1.0f / (float)(gj + 1);
        union { uint4 u; __nv_bfloat16 h[8]; } ph, pl;
#pragma unroll
        for (int r = 0; r < 8; r++) {
            int gi = iBase + i0 + r;
            float v = (gi < gj) ? acc[r][c] * (float)(gi + 1) * rj : 0.f;
            __nv_bfloat16 hi = __float2bfloat16(v);
            ph.h[r] = hi;
            pl.h[r] = __float2bfloat16(v - __bfloat162float(hi));
        }
        size_t off = (size_t)gj * LL + iBase + i0;
        *(uint4*)&Ah[off] = ph.u;
        *(uint4*)&Al[off] = pl.u;
    }
}

// ---------------------------------------------------------------------------
// Kernel 1b: transpose+split bert_x -> Xt[b][h][i] (bf16 hi/lo)
// ---------------------------------------------------------------------------
__global__ void __launch_bounds__(256) k_xprep(const float* __restrict__ bx) {
    __shared__ float t[32][33];
    int i0 = blockIdx.x * 32, h0 = blockIdx.y * 32, b = blockIdx.z;
    for (int r = threadIdx.y; r < 32; r += 8)
        t[r][threadIdx.x] = bx[((size_t)b * LL + i0 + r) * HH + h0 + threadIdx.x];
    __syncthreads();
    for (int r = threadIdx.y; r < 32; r += 8) {
        float v = t[threadIdx.x][r];
        __nv_bfloat16 hi = __float2bfloat16(v);
        size_t off = ((size_t)b * HH + h0 + r) * LL + i0 + threadIdx.x;
        g_Xh[off] = hi;
        g_Xl[off] = __float2bfloat16(v - __bfloat162float(hi));
    }
}

// ---------------------------------------------------------------------------
// HMMA helpers (base-target safe: mma.sync + ldmatrix, sm_80 features)
// ---------------------------------------------------------------------------
__device__ __forceinline__ uint32_t smem_u32(const void* p) {
    uint32_t a;
    asm("{ .reg .u64 t; cvta.to.shared.u64 t, %1; cvt.u32.u64 %0, t; }"
        : "=r"(a) : "l"(p));
    return a;
}
__device__ __forceinline__ void ldm_x4(uint32_t& r0, uint32_t& r1, uint32_t& r2,
                                       uint32_t& r3, uint32_t addr) {
    asm volatile("ldmatrix.sync.aligned.m8n8.x4.shared.b16 {%0,%1,%2,%3}, [%4];"
                 : "=r"(r0), "=r"(r1), "=r"(r2), "=r"(r3) : "r"(addr));
}
__device__ __forceinline__ void mma16816(float* c, uint32_t a0, uint32_t a1,
                                         uint32_t a2, uint32_t a3, uint32_t b0,
                                         uint32_t b1) {
    asm volatile(
        "mma.sync.aligned.m16n8k16.row.col.f32.bf16.bf16.f32 "
        "{%0,%1,%2,%3}, {%4,%5,%6,%7}, {%8,%9}, {%0,%1,%2,%3};"
        : "+f"(c[0]), "+f"(c[1]), "+f"(c[2]), "+f"(c[3])
        : "r"(a0), "r"(a1), "r"(a2), "r"(a3), "r"(b0), "r"(b1));
}

// ---------------------------------------------------------------------------
// Kernel 2 (HMMA): out[b,j,h] = bx[b,j,h] + sum_i A'[b,j,i] * X^T[b,h,i]
// CTA: 128(j) x 128(h); 8 warps in 2(j) x 4(h); warp tile 64x32.
// K-chunks of 64; smem row stride 144B -> conflict-free ldmatrix.
// 2-term bf16 split: 3 products AhBh + AhBl + AlBh.
// ---------------------------------------------------------------------------
#define STRB     144                       // smem row stride (bytes)
#define TILE_B   (128 * STRB)              // 18432 B per tile
#define OFF_AH   0
#define OFF_AL   TILE_B
#define OFF_XH   (2 * TILE_B)
#define OFF_XL   (3 * TILE_B)
#define SMEM_TOT (4 * TILE_B)              // 73728 B

__global__ void __launch_bounds__(256, 2) k_apply_mma(const float* __restrict__ bx,
                                                      float* __restrict__ out) {
    extern __shared__ char smem[];
    uint32_t sb = smem_u32(smem);
    int tid = threadIdx.x, wid = tid >> 5, l = tid & 31;
    int hT = blockIdx.x, jT = blockIdx.y, b = blockIdx.z;
    int jBase = jT * 128, hBase = hT * 128;
    int wm = wid & 1, wn = wid >> 1;       // warp tile: (wm*64, wn*32)

    const __nv_bfloat16* Agh = g_Ah + ((size_t)(b * LL + jBase)) * LL;
    const __nv_bfloat16* Agl = g_Al + ((size_t)(b * LL + jBase)) * LL;
    const __nv_bfloat16* Xgh = g_Xh + ((size_t)(b * HH + hBase)) * LL;
    const __nv_bfloat16* Xgl = g_Xl + ((size_t)(b * HH + hBase)) * LL;

    float acc[4][4][4];                    // [mfrag][nfrag][4]
#pragma unroll
    for (int m = 0; m < 4; m++)
#pragma unroll
        for (int n = 0; n < 4; n++)
#pragma unroll
            for (int k = 0; k < 4; k++) acc[m][n][k] = 0.f;

    // ldmatrix lane->address components (within a warp)
    // A (x4): rows m0-15, k chunks 0/16B:  row=(l&15), kb=(l>>4)*16
    uint32_t aLane = (uint32_t)((wm * 64 + (l & 15)) * STRB + (l >> 4) * 16);
    // X (x4): lanes 0-7: n0-7/k0; 8-15: n0-7/k16B; 16-23: n8-15/k0; 24-31: n8-15/k16B
    uint32_t xLane = (uint32_t)((wn * 32 + (l & 7) + ((l >> 4) * 8)) * STRB +
                                ((l >> 3) & 1) * 16);

    int nCh = (jT + 1) * 2;                // causal: i < (jT+1)*128
    for (int ck = 0; ck < nCh; ck++) {
        size_t kOff = (size_t)ck * 64;
        // fill 4 tiles: 128 rows x 64 bf16 (8 x uint4 per row)
#pragma unroll
        for (int v = 0; v < 4; v++) {
            int idx = v * 256 + tid;
            int row = idx >> 3, c = idx & 7;
            uint32_t so = (uint32_t)(row * STRB + c * 16);
            *(uint4*)(smem + OFF_AH + so) = *((const uint4*)(Agh + (size_t)row * LL + kOff) + c);
            *(uint4*)(smem + OFF_AL + so) = *((const uint4*)(Agl + (size_t)row * LL + kOff) + c);
            *(uint4*)(smem + OFF_XH + so) = *((const uint4*)(Xgh + (size_t)row * LL + kOff) + c);
            *(uint4*)(smem + OFF_XL + so) = *((const uint4*)(Xgl + (size_t)row * LL + kOff) + c);
        }
        __syncthreads();

#pragma unroll
        for (int s = 0; s < 4; s++) {      // 4 k16 steps per 64-chunk
            uint32_t ks = (uint32_t)(s * 32);
            // B fragments: hi & lo, 4 nfrags via 2 x4-ldmatrix each
            uint32_t bh[8], bl[8];
            ldm_x4(bh[0], bh[1], bh[2], bh[3], sb + OFF_XH + xLane + ks);
            ldm_x4(bh[4], bh[5], bh[6], bh[7], sb + OFF_XH + xLane + ks + 16 * STRB);
            ldm_x4(bl[0], bl[1], bl[2], bl[3], sb + OFF_XL + xLane + ks);
            ldm_x4(bl[4], bl[5], bl[6], bl[7], sb + OFF_XL + xLane + ks + 16 * STRB);
#pragma unroll
            for (int m = 0; m < 4; m++) {
                uint32_t ah0, ah1, ah2, ah3, al0, al1, al2, al3;
                uint32_t ao = aLane + (uint32_t)(m * 16 * STRB) + ks;
                ldm_x4(ah0, ah1, ah2, ah3, sb + OFF_AH + ao);
                ldm_x4(al0, al1, al2, al3, sb + OFF_AL + ao);
#pragma unroll
                for (int n = 0; n < 4; n++) {
                    uint32_t b0h = bh[(n & 1) ? 2 : 0 + ((n >> 1) * 4)];
                    // explicit indexing (avoid precedence surprises):
                    uint32_t i0 = (uint32_t)((n >> 1) * 4 + (n & 1) * 2);
                    b0h = bh[i0];
                    uint32_t b1h = bh[i0 + 1];
                    uint32_t b0l = bl[i0];
                    uint32_t b1l = bl[i0 + 1];
                    mma16816(acc[m][n], ah0, ah1, ah2, ah3, b0h, b1h);
                    mma16816(acc[m][n], ah0, ah1, ah2, ah3, b0l, b1l);
                    mma16816(acc[m][n], al0, al1, al2, al3, b0h, b1h);
                }
            }
        }
        __syncthreads();
    }

    // epilogue: c0,c1 -> (m=l/4, n=(l&3)*2), c2,c3 -> (m+8, same n)
#pragma unroll
    for (int m = 0; m < 4; m++) {
#pragma unroll
        for (int n = 0; n < 4; n++) {
            int gm = jBase + wm * 64 + m * 16 + (l >> 2);
            int gn = hBase + wn * 32 + n * 8 + (l & 3) * 2;
            size_t o0 = ((size_t)b * LL + gm) * HH + gn;
            size_t o1 = ((size_t)b * LL + gm + 8) * HH + gn;
            float2 x0 = *(const float2*)(bx + o0);
            float2 x1 = *(const float2*)(bx + o1);
            *(float2*)(out + o0) = make_float2(x0.x + acc[m][n][0], x0.y + acc[m][n][1]);
            *(float2*)(out + o1) = make_float2(x1.x + acc[m][n][2], x1.y + acc[m][n][3]);
        }
    }
}

// ---------------------------------------------------------------------------
extern "C" void kernel_launch(void* const* d_in, const int* in_sizes, int n_in,
                              void* d_out, int out_size) {
    const float* bert_x = nullptr;
    const void*  x      = nullptr;
    const float* ae     = nullptr;
    const float* w      = nullptr;
    for (int i = 0; i < n_in; i++) {
        switch (in_sizes[i]) {
            case 25165824: bert_x = (const float*)d_in[i]; break;
            case 32768:    x      = d_in[i];               break;
            case 1920000:  ae     = (const float*)d_in[i]; break;
            case 4096:     w      = (const float*)d_in[i]; break;
            default: break;
        }
    }
    float* out = (float*)d_out;

    cudaFuncSetAttribute(k_apply_mma,
                         cudaFuncAttributeMaxDynamicSharedMemorySize, SMEM_TOT);

    k_gather<<<(BB * LL) / 4, 256>>>(ae, x, w);
    k_scores<<<dim3(LL / 128, LL / 128, BB), 256>>>();
    k_xprep<<<dim3(LL / 32, HH / 32, BB), dim3(32, 8)>>>(bert_x);
    k_apply_mma<<<dim3(HH / 128, LL / 128, BB), 256, SMEM_TOT>>>(bert_x, out);
}

// round 5
// speedup vs baseline: 1.9348x; 1.0322x over previous
#include <cuda_runtime.h>
#include <cuda_bf16.h>
#include <cstdint>

#define BB 16
#define LL 2048
#define HH 768
#define DD 64
#define VV 30000

// ---------------------------------------------------------------------------
// Device-global scratch (no allocation allowed in kernel_launch)
// ---------------------------------------------------------------------------
__device__ float g_E[(size_t)BB * LL * DD];                    // 8 MB
__device__ float g_F[(size_t)BB * LL * DD];                    // 8 MB
__device__ __nv_bfloat16 g_Ah[(size_t)BB * LL * LL];           // scores^T hi [b][j][i]  128 MB
__device__ __nv_bfloat16 g_Al[(size_t)BB * LL * LL];           // scores^T lo            128 MB
__device__ __nv_bfloat16 g_Xh[(size_t)BB * HH * LL];           // bert_x^T hi [b][h][i]  50 MB
__device__ __nv_bfloat16 g_Xl[(size_t)BB * HH * LL];           // bert_x^T lo            50 MB

// ---------------------------------------------------------------------------
// Kernel 0: gather E = ae[x], F = E @ w
// ---------------------------------------------------------------------------
__global__ void __launch_bounds__(256) k_gather(const float* __restrict__ ae,
                                                const void* __restrict__ xraw,
                                                const float* __restrict__ w) {
    __shared__ float ws[64 * 64];
    __shared__ float es[4][64];
    for (int t = threadIdx.x; t < 64 * 64; t += 256) ws[t] = w[t];

    const int* xi = (const int*)xraw;
    bool is64 = true;
#pragma unroll
    for (int k = 0; k < 32; k++)
        if (xi[2 * k + 1] != 0) is64 = false;

    int sub = threadIdx.x >> 6;
    int d   = threadIdx.x & 63;
    int row = blockIdx.x * 4 + sub;

    long long tok;
    if (is64) tok = ((const long long*)xraw)[row];
    else      tok = (long long)xi[row];
    if (tok < 0) tok = 0;
    if (tok >= VV) tok = VV - 1;

    float e = ae[(size_t)tok * 64 + d];
    es[sub][d] = e;
    g_E[(size_t)row * 64 + d] = e;
    __syncthreads();
    float f = 0.f;
#pragma unroll
    for (int k = 0; k < 64; k++) f += es[sub][k] * ws[k * 64 + d];
    g_F[(size_t)row * 64 + d] = f;
}

// ---------------------------------------------------------------------------
// Kernel 1: scores (fp32 SIMT), epilogue writes TRANSPOSED bf16 hi/lo
//   A'[b][j][i] = (F[b,i].E[b,j]) * (i+1)/(j+1)  for i<j else 0
// ---------------------------------------------------------------------------
__global__ void __launch_bounds__(256) k_scores() {
    int jT = blockIdx.x, iT = blockIdx.y, b = blockIdx.z;
    if (iT > jT) return;

    __shared__ float Fs[32][132];
    __shared__ float Es[32][132];

    int iBase = iT * 128, jBase = jT * 128;
    const float* Fg = g_F + ((size_t)b * LL + iBase) * 64;
    const float* Eg = g_E + ((size_t)b * LL + jBase) * 64;

    int tx = threadIdx.x & 15, ty = threadIdx.x >> 4;
    int i0 = ty * 8, j0 = tx * 8;

    float acc[8][8];
#pragma unroll
    for (int r = 0; r < 8; r++)
#pragma unroll
        for (int c = 0; c < 8; c++) acc[r][c] = 0.f;

    for (int kp = 0; kp < 2; kp++) {
        for (int t = threadIdx.x; t < 128 * 32; t += 256) {
            int r = t >> 5, k = t & 31;
            Fs[k][r] = Fg[(size_t)r * 64 + kp * 32 + k];
            Es[k][r] = Eg[(size_t)r * 64 + kp * 32 + k];
        }
        __syncthreads();
#pragma unroll
        for (int k = 0; k < 32; k++) {
            float4 a0 = *(const float4*)&Fs[k][i0];
            float4 a1 = *(const float4*)&Fs[k][i0 + 4];
            float4 b0 = *(const float4*)&Es[k][j0];
            float4 b1 = *(const float4*)&Es[k][j0 + 4];
            float av[8] = {a0.x, a0.y, a0.z, a0.w, a1.x, a1.y, a1.z, a1.w};
            float bv[8] = {b0.x, b0.y, b0.z, b0.w, b1.x, b1.y, b1.z, b1.w};
#pragma unroll
            for (int r = 0; r < 8; r++)
#pragma unroll
                for (int c = 0; c < 8; c++) acc[r][c] += av[r] * bv[c];
        }
        __syncthreads();
    }

    __nv_bfloat16* Ah = g_Ah + (size_t)b * LL * LL;
    __nv_bfloat16* Al = g_Al + (size_t)b * LL * LL;
#pragma unroll
    for (int c = 0; c < 8; c++) {
        int gj = jBase + j0 + c;
        float rj = 1.0f / (float)(gj + 1);
        union { uint4 u; __nv_bfloat16 h[8]; } ph, pl;
#pragma unroll
        for (int r = 0; r < 8; r++) {
            int gi = iBase + i0 + r;
            float v = (gi < gj) ? acc[r][c] * (float)(gi + 1) * rj : 0.f;
            __nv_bfloat16 hi = __float2bfloat16(v);
            ph.h[r] = hi;
            pl.h[r] = __float2bfloat16(v - __bfloat162float(hi));
        }
        size_t off = (size_t)gj * LL + iBase + i0;
        *(uint4*)&Ah[off] = ph.u;
        *(uint4*)&Al[off] = pl.u;
    }
}

// ---------------------------------------------------------------------------
// Kernel 1b: transpose+split bert_x -> Xt[b][h][i] (bf16 hi/lo)
// ---------------------------------------------------------------------------
__global__ void __launch_bounds__(256) k_xprep(const float* __restrict__ bx) {
    __shared__ float t[32][33];
    int i0 = blockIdx.x * 32, h0 = blockIdx.y * 32, b = blockIdx.z;
    for (int r = threadIdx.y; r < 32; r += 8)
        t[r][threadIdx.x] = bx[((size_t)b * LL + i0 + r) * HH + h0 + threadIdx.x];
    __syncthreads();
    for (int r = threadIdx.y; r < 32; r += 8) {
        float v = t[threadIdx.x][r];
        __nv_bfloat16 hi = __float2bfloat16(v);
        size_t off = ((size_t)b * HH + h0 + r) * LL + i0 + threadIdx.x;
        g_Xh[off] = hi;
        g_Xl[off] = __float2bfloat16(v - __bfloat162float(hi));
    }
}

// ---------------------------------------------------------------------------
// HMMA + cp.async helpers (base-target safe, sm_80 features)
// ---------------------------------------------------------------------------
__device__ __forceinline__ uint32_t smem_u32(const void* p) {
    uint32_t a;
    asm("{ .reg .u64 t; cvta.to.shared.u64 t, %1; cvt.u32.u64 %0, t; }"
        : "=r"(a) : "l"(p));
    return a;
}
__device__ __forceinline__ void ldm_x4(uint32_t& r0, uint32_t& r1, uint32_t& r2,
                                       uint32_t& r3, uint32_t addr) {
    asm volatile("ldmatrix.sync.aligned.m8n8.x4.shared.b16 {%0,%1,%2,%3}, [%4];"
                 : "=r"(r0), "=r"(r1), "=r"(r2), "=r"(r3) : "r"(addr));
}
__device__ __forceinline__ void mma16816(float* c, uint32_t a0, uint32_t a1,
                                         uint32_t a2, uint32_t a3, uint32_t b0,
                                         uint32_t b1) {
    asm volatile(
        "mma.sync.aligned.m16n8k16.row.col.f32.bf16.bf16.f32 "
        "{%0,%1,%2,%3}, {%4,%5,%6,%7}, {%8,%9}, {%0,%1,%2,%3};"
        : "+f"(c[0]), "+f"(c[1]), "+f"(c[2]), "+f"(c[3])
        : "r"(a0), "r"(a1), "r"(a2), "r"(a3), "r"(b0), "r"(b1));
}
__device__ __forceinline__ void cp16(uint32_t s, const void* g) {
    asm volatile("cp.async.cg.shared.global [%0], [%1], 16;" :: "r"(s), "l"(g));
}
#define CP_COMMIT()  asm volatile("cp.async.commit_group;" ::: "memory")
#define CP_WAIT(n)   asm volatile("cp.async.wait_group %0;" :: "n"(n) : "memory")

// ---------------------------------------------------------------------------
// Kernel 2 (HMMA, 2-stage cp.async pipeline):
//   out[b,j,h] = bx[b,j,h] + sum_i A'[b,j,i] * X^T[b,h,i]
// CTA: 128(j) x 128(h); 8 warps in 2(j) x 4(h); warp tile 64x32.
// K-chunks of 64; smem row stride 144B -> conflict-free ldmatrix.
// 2-term bf16 split: 3 products AhBh + AhBl + AlBh.
// ---------------------------------------------------------------------------
#define STRB     144                       // smem row stride (bytes)
#define TILE_B   (128 * STRB)              // 18432 B per tile
#define OFF_AH   0
#define OFF_AL   TILE_B
#define OFF_XH   (2 * TILE_B)
#define OFF_XL   (3 * TILE_B)
#define STAGE_B  (4 * TILE_B)              // 73728 B per stage
#define SMEM_TOT (2 * STAGE_B)             // 147456 B

__global__ void __launch_bounds__(256, 1) k_apply_mma(const float* __restrict__ bx,
                                                      float* __restrict__ out) {
    extern __shared__ char smem[];
    uint32_t sb = smem_u32(smem);
    int tid = threadIdx.x, wid = tid >> 5, l = tid & 31;
    int hT = blockIdx.x, b = blockIdx.z;
    int jT = (int)gridDim.y - 1 - (int)blockIdx.y;   // longest-first scheduling
    int jBase = jT * 128, hBase = hT * 128;
    int wm = wid & 1, wn = wid >> 1;       // warp tile: (wm*64, wn*32)

    const __nv_bfloat16* Agh = g_Ah + ((size_t)(b * LL + jBase)) * LL;
    const __nv_bfloat16* Agl = g_Al + ((size_t)(b * LL + jBase)) * LL;
    const __nv_bfloat16* Xgh = g_Xh + ((size_t)(b * HH + hBase)) * LL;
    const __nv_bfloat16* Xgl = g_Xl + ((size_t)(b * HH + hBase)) * LL;

    // per-thread fill coordinates (16 cp.async per chunk: 4 per tile)
    int fRow = tid >> 3, fCol = tid & 7;   // row 0..31 (x4 blocks of 32), col 0..7
    uint32_t fOff = (uint32_t)(fRow * STRB + fCol * 16);
    size_t   gRowOff = (size_t)fRow * LL;

    float acc[4][4][4];
#pragma unroll
    for (int m = 0; m < 4; m++)
#pragma unroll
        for (int n = 0; n < 4; n++)
#pragma unroll
            for (int k = 0; k < 4; k++) acc[m][n][k] = 0.f;

    uint32_t aLane = (uint32_t)((wm * 64 + (l & 15)) * STRB + (l >> 4) * 16);
    uint32_t xLane = (uint32_t)((wn * 32 + (l & 7) + ((l >> 4) * 8)) * STRB +
                                ((l >> 3) & 1) * 16);

    int nCh = (jT + 1) * 2;                // causal: i < (jT+1)*128

    // ---- fill helper (macro to keep cp.async flat) ----
#define FILL_CHUNK(CK, ST)                                                        \
    do {                                                                          \
        uint32_t _sb = sb + (uint32_t)(ST) * STAGE_B;                             \
        size_t _k = (size_t)(CK) * 64;                                            \
        _Pragma("unroll")                                                         \
        for (int _v = 0; _v < 4; _v++) {                                          \
            uint32_t _so = fOff + (uint32_t)(_v * 32 * STRB);                     \
            size_t _go = gRowOff + (size_t)(_v * 32) * LL + _k + fCol * 8;        \
            cp16(_sb + OFF_AH + _so, Agh + _go);                                  \
            cp16(_sb + OFF_AL + _so, Agl + _go);                                  \
            cp16(_sb + OFF_XH + _so, Xgh + _go);                                  \
            cp16(_sb + OFF_XL + _so, Xgl + _go);                                  \
        }                                                                         \
        CP_COMMIT();                                                              \
    } while (0)

    FILL_CHUNK(0, 0);

    for (int ck = 0; ck < nCh; ck++) {
        int st = ck & 1;
        if (ck + 1 < nCh) {
            FILL_CHUNK(ck + 1, st ^ 1);
            CP_WAIT(1);
        } else {
            CP_WAIT(0);
        }
        __syncthreads();

        uint32_t base = sb + (uint32_t)st * STAGE_B;
#pragma unroll
        for (int s = 0; s < 4; s++) {
            uint32_t ks = (uint32_t)(s * 32);
            uint32_t bh[8], bl[8];
            ldm_x4(bh[0], bh[1], bh[2], bh[3], base + OFF_XH + xLane + ks);
            ldm_x4(bh[4], bh[5], bh[6], bh[7], base + OFF_XH + xLane + ks + 16 * STRB);
            ldm_x4(bl[0], bl[1], bl[2], bl[3], base + OFF_XL + xLane + ks);
            ldm_x4(bl[4], bl[5], bl[6], bl[7], base + OFF_XL + xLane + ks + 16 * STRB);
#pragma unroll
            for (int m = 0; m < 4; m++) {
                uint32_t ah0, ah1, ah2, ah3, al0, al1, al2, al3;
                uint32_t ao = aLane + (uint32_t)(m * 16 * STRB) + ks;
                ldm_x4(ah0, ah1, ah2, ah3, base + OFF_AH + ao);
                ldm_x4(al0, al1, al2, al3, base + OFF_AL + ao);
#pragma unroll
                for (int n = 0; n < 4; n++) {
                    uint32_t i0 = (uint32_t)((n >> 1) * 4 + (n & 1) * 2);
                    uint32_t b0h = bh[i0], b1h = bh[i0 + 1];
                    uint32_t b0l = bl[i0], b1l = bl[i0 + 1];
                    mma16816(acc[m][n], ah0, ah1, ah2, ah3, b0h, b1h);
                    mma16816(acc[m][n], ah0, ah1, ah2, ah3, b0l, b1l);
                    mma16816(acc[m][n], al0, al1, al2, al3, b0h, b1h);
                }
            }
        }
        __syncthreads();   // stage st free for reuse (refilled at iter ck+1)
    }

    // epilogue: c0,c1 -> (m=l/4, n=(l&3)*2), c2,c3 -> (m+8, same n)
#pragma unroll
    for (int m = 0; m < 4; m++) {
#pragma unroll
        for (int n = 0; n < 4; n++) {
            int gm = jBase + wm * 64 + m * 16 + (l >> 2);
            int gn = hBase + wn * 32 + n * 8 + (l & 3) * 2;
            size_t o0 = ((size_t)b * LL + gm) * HH + gn;
            size_t o1 = ((size_t)b * LL + gm + 8) * HH + gn;
            float2 x0 = *(const float2*)(bx + o0);
            float2 x1 = *(const float2*)(bx + o1);
            *(float2*)(out + o0) = make_float2(x0.x + acc[m][n][0], x0.y + acc[m][n][1]);
            *(float2*)(out + o1) = make_float2(x1.x + acc[m][n][2], x1.y + acc[m][n][3]);
        }
    }
}

// ---------------------------------------------------------------------------
extern "C" void kernel_launch(void* const* d_in, const int* in_sizes, int n_in,
                              void* d_out, int out_size) {
    const float* bert_x = nullptr;
    const void*  x      = nullptr;
    const float* ae     = nullptr;
    const float* w      = nullptr;
    for (int i = 0; i < n_in; i++) {
        switch (in_sizes[i]) {
            case 25165824: bert_x = (const float*)d_in[i]; break;
            case 32768:    x      = d_in[i];               break;
            case 1920000:  ae     = (const float*)d_in[i]; break;
            case 4096:     w      = (const float*)d_in[i]; break;
            default: break;
        }
    }
    float* out = (float*)d_out;

    cudaFuncSetAttribute(k_apply_mma,
                         cudaFuncAttributeMaxDynamicSharedMemorySize, SMEM_TOT);

    k_gather<<<(BB * LL) / 4, 256>>>(ae, x, w);
    k_scores<<<dim3(LL / 128, LL / 128, BB), 256>>>();
    k_xprep<<<dim3(LL / 32, HH / 32, BB), dim3(32, 8)>>>(bert_x);
    k_apply_mma<<<dim3(HH / 128, LL / 128, BB), 256, SMEM_TOT>>>(bert_x, out);
}

// round 6
// speedup vs baseline: 3.9389x; 2.0358x over previous
#include <cuda_runtime.h>
#include <cuda_bf16.h>
#include <cstdint>

#define BB 16
#define LL 2048
#define HH 768
#define DD 64
#define VV 30000
#define CC 128               // chunk length
#define NC 16                // number of chunks

// ---------------------------------------------------------------------------
// Device-global scratch
// ---------------------------------------------------------------------------
__device__ __nv_bfloat16 g_Eph[(size_t)BB * LL * DD];   // E' hi  [b][l][d]
__device__ __nv_bfloat16 g_Epl[(size_t)BB * LL * DD];   // E' lo
__device__ __nv_bfloat16 g_Fph[(size_t)BB * LL * DD];   // F' hi  [b][l][d]
__device__ __nv_bfloat16 g_Fpl[(size_t)BB * LL * DD];   // F' lo
__device__ __nv_bfloat16 g_Fth[(size_t)BB * DD * LL];   // F' hi  [b][d][l]
__device__ __nv_bfloat16 g_Ftl[(size_t)BB * DD * LL];   // F' lo
__device__ __nv_bfloat16 g_Xh[(size_t)BB * HH * LL];    // X hi   [b][h][l]
__device__ __nv_bfloat16 g_Xl[(size_t)BB * HH * LL];    // X lo
__device__ float         g_T [(size_t)BB * NC * HH * DD];  // chunk sums fp32
__device__ __nv_bfloat16 g_Sh[(size_t)BB * NC * HH * DD];  // excl prefix hi [b][c][h][d]
__device__ __nv_bfloat16 g_Sl[(size_t)BB * NC * HH * DD];  // excl prefix lo

// ---------------------------------------------------------------------------
// helpers
// ---------------------------------------------------------------------------
__device__ __forceinline__ uint32_t smem_u32(const void* p) {
    uint32_t a;
    asm("{ .reg .u64 t; cvta.to.shared.u64 t, %1; cvt.u32.u64 %0, t; }"
        : "=r"(a) : "l"(p));
    return a;
}
__device__ __forceinline__ void ldm_x4(uint32_t& r0, uint32_t& r1, uint32_t& r2,
                                       uint32_t& r3, uint32_t addr) {
    asm volatile("ldmatrix.sync.aligned.m8n8.x4.shared.b16 {%0,%1,%2,%3}, [%4];"
                 : "=r"(r0), "=r"(r1), "=r"(r2), "=r"(r3) : "r"(addr));
}
__device__ __forceinline__ void mma16816(float* c, uint32_t a0, uint32_t a1,
                                         uint32_t a2, uint32_t a3, uint32_t b0,
                                         uint32_t b1) {
    asm volatile(
        "mma.sync.aligned.m16n8k16.row.col.f32.bf16.bf16.f32 "
        "{%0,%1,%2,%3}, {%4,%5,%6,%7}, {%8,%9}, {%0,%1,%2,%3};"
        : "+f"(c[0]), "+f"(c[1]), "+f"(c[2]), "+f"(c[3])
        : "r"(a0), "r"(a1), "r"(a2), "r"(a3), "r"(b0), "r"(b1));
}
__device__ __forceinline__ void cp16(uint32_t s, const void* g) {
    asm volatile("cp.async.cg.shared.global [%0], [%1], 16;" :: "r"(s), "l"(g));
}
#define CP_COMMIT()  asm volatile("cp.async.commit_group;" ::: "memory")
#define CP_WAIT(n)   asm volatile("cp.async.wait_group %0;" :: "n"(n) : "memory")

__device__ __forceinline__ void split2pack(float a, float b, uint32_t& hi,
                                           uint32_t& lo) {
    __nv_bfloat16 ha = __float2bfloat16(a), hb = __float2bfloat16(b);
    __nv_bfloat16 la = __float2bfloat16(a - __bfloat162float(ha));
    __nv_bfloat16 lb = __float2bfloat16(b - __bfloat162float(hb));
    hi = (uint32_t)__bfloat16_as_ushort(ha) |
         ((uint32_t)__bfloat16_as_ushort(hb) << 16);
    lo = (uint32_t)__bfloat16_as_ushort(la) |
         ((uint32_t)__bfloat16_as_ushort(lb) << 16);
}

#define STRB  144   // standard 128x64-bf16 tile row stride (bytes)
#define TILE  18432 // 128*144
#define STRP  272   // P tile (128x128 bf16) row stride
#define PTILE 34816 // 128*272

// 4 k16-steps GEMM on a 64-wide K slab. acc[4][4][4], warp tile 64x32.
// aMstr: byte stride between m16 fragments (16*STRB or 16*STRP).
__device__ __forceinline__ void gemm4(float (&acc)[4][4][4], uint32_t aH,
                                      uint32_t aL, uint32_t bH, uint32_t bL,
                                      uint32_t aMstr) {
#pragma unroll
    for (int s = 0; s < 4; s++) {
        uint32_t ks = (uint32_t)(s * 32);
        uint32_t bhf[8], blf[8];
        ldm_x4(bhf[0], bhf[1], bhf[2], bhf[3], bH + ks);
        ldm_x4(bhf[4], bhf[5], bhf[6], bhf[7], bH + ks + 16 * STRB);
        ldm_x4(blf[0], blf[1], blf[2], blf[3], bL + ks);
        ldm_x4(blf[4], blf[5], blf[6], blf[7], bL + ks + 16 * STRB);
#pragma unroll
        for (int m = 0; m < 4; m++) {
            uint32_t ah0, ah1, ah2, ah3, al0, al1, al2, al3;
            ldm_x4(ah0, ah1, ah2, ah3, aH + m * aMstr + ks);
            ldm_x4(al0, al1, al2, al3, aL + m * aMstr + ks);
#pragma unroll
            for (int n = 0; n < 4; n++) {
                uint32_t i0 = (uint32_t)((n >> 1) * 4 + (n & 1) * 2);
                mma16816(acc[m][n], ah0, ah1, ah2, ah3, bhf[i0], bhf[i0 + 1]);
                mma16816(acc[m][n], ah0, ah1, ah2, ah3, blf[i0], blf[i0 + 1]);
                mma16816(acc[m][n], al0, al1, al2, al3, bhf[i0], bhf[i0 + 1]);
            }
        }
    }
}

// ---------------------------------------------------------------------------
// K1: per row: E=ae[x], F=E@w; E'=E/(l+1), F'=F*(l+1); split+store 3 layouts.
// ---------------------------------------------------------------------------
__global__ void __launch_bounds__(256) k_prep(const float* __restrict__ ae,
                                              const void* __restrict__ xraw,
                                              const float* __restrict__ w) {
    __shared__ float ws[64 * 64];
    __shared__ float es[4][64];
    for (int t = threadIdx.x; t < 64 * 64; t += 256) ws[t] = w[t];

    const int* xi = (const int*)xraw;
    bool is64 = true;
#pragma unroll
    for (int k = 0; k < 32; k++)
        if (xi[2 * k + 1] != 0) is64 = false;

    int sub = threadIdx.x >> 6;
    int d   = threadIdx.x & 63;
    int row = blockIdx.x * 4 + sub;
    int b   = row >> 11, l = row & (LL - 1);

    long long tok;
    if (is64) tok = ((const long long*)xraw)[row];
    else      tok = (long long)xi[row];
    if (tok < 0) tok = 0;
    if (tok >= VV) tok = VV - 1;

    float e = ae[(size_t)tok * 64 + d];
    es[sub][d] = e;
    __syncthreads();
    float f = 0.f;
#pragma unroll
    for (int k = 0; k < 64; k++) f += es[sub][k] * ws[k * 64 + d];

    float sc = (float)(l + 1);
    float ep = e / sc;
    float fp = f * sc;

    __nv_bfloat16 eh = __float2bfloat16(ep);
    __nv_bfloat16 el = __float2bfloat16(ep - __bfloat162float(eh));
    __nv_bfloat16 fh = __float2bfloat16(fp);
    __nv_bfloat16 fl = __float2bfloat16(fp - __bfloat162float(fh));

    size_t ro = (size_t)row * 64 + d;
    g_Eph[ro] = eh; g_Epl[ro] = el;
    g_Fph[ro] = fh; g_Fpl[ro] = fl;
    size_t to = ((size_t)b * 64 + d) * LL + l;
    g_Fth[to] = fh; g_Ftl[to] = fl;
}

// ---------------------------------------------------------------------------
// K1b: transpose+split bert_x -> Xt[b][h][l] bf16 hi/lo
// ---------------------------------------------------------------------------
__global__ void __launch_bounds__(256) k_xprep(const float* __restrict__ bx) {
    __shared__ float t[32][33];
    int i0 = blockIdx.x * 32, h0 = blockIdx.y * 32, b = blockIdx.z;
    for (int r = threadIdx.y; r < 32; r += 8)
        t[r][threadIdx.x] = bx[((size_t)b * LL + i0 + r) * HH + h0 + threadIdx.x];
    __syncthreads();
    for (int r = threadIdx.y; r < 32; r += 8) {
        float v = t[threadIdx.x][r];
        __nv_bfloat16 hi = __float2bfloat16(v);
        size_t off = ((size_t)b * HH + h0 + r) * LL + i0 + threadIdx.x;
        g_Xh[off] = hi;
        g_Xl[off] = __float2bfloat16(v - __bfloat162float(hi));
    }
}

// ---------------------------------------------------------------------------
// K2: chunk sums  T[b][c][h][d] = sum_{i in chunk} X[i,h] * F'[i,d]
// CTA=(hT,c,b): out 128(h) x 64(d), K=128(i) in two 64-slabs. 8 warps 4x2,
// warp tile 32x32.
// ---------------------------------------------------------------------------
#define K2_AH 0
#define K2_AL TILE
#define K2_BH (2 * TILE)
#define K2_BL (2 * TILE + 9216)
#define K2_SMEM (2 * TILE + 2 * 9216)

__global__ void __launch_bounds__(256) k_chunksum() {
    extern __shared__ char smem[];
    uint32_t sb = smem_u32(smem);
    int tid = threadIdx.x, wid = tid >> 5, l = tid & 31;
    int hT = blockIdx.x, c = blockIdx.y, b = blockIdx.z;
    int hBase = hT * 128;
    int wm = wid & 3, wn = wid >> 2;

    float acc[2][4][4];
#pragma unroll
    for (int m = 0; m < 2; m++)
#pragma unroll
        for (int n = 0; n < 4; n++)
#pragma unroll
            for (int k = 0; k < 4; k++) acc[m][n][k] = 0.f;

    uint32_t aLane = (uint32_t)((wm * 32 + (l & 15)) * STRB + (l >> 4) * 16);
    uint32_t xLane = (uint32_t)((wn * 32 + (l & 7) + ((l >> 4) * 8)) * STRB +
                                ((l >> 3) & 1) * 16);

    for (int subk = 0; subk < 2; subk++) {
        size_t kOff = (size_t)c * CC + subk * 64;
        // A: Xt 128 rows(h) x 64
#pragma unroll
        for (int v = 0; v < 4; v++) {
            int idx = v * 256 + tid;
            int row = idx >> 3, col = idx & 7;
            uint32_t so = (uint32_t)(row * STRB + col * 16);
            size_t go = ((size_t)(b * HH + hBase + row)) * LL + kOff + col * 8;
            cp16(sb + K2_AH + so, g_Xh + go);
            cp16(sb + K2_AL + so, g_Xl + go);
        }
        // B: F't 64 rows(d) x 64
#pragma unroll
        for (int v = 0; v < 2; v++) {
            int idx = v * 256 + tid;
            int row = idx >> 3, col = idx & 7;
            uint32_t so = (uint32_t)(row * STRB + col * 16);
            size_t go = ((size_t)(b * DD + row)) * LL + kOff + col * 8;
            cp16(sb + K2_BH + so, g_Fth + go);
            cp16(sb + K2_BL + so, g_Ftl + go);
        }
        CP_COMMIT();
        CP_WAIT(0);
        __syncthreads();

#pragma unroll
        for (int s = 0; s < 4; s++) {
            uint32_t ks = (uint32_t)(s * 32);
            uint32_t bhf[8], blf[8];
            ldm_x4(bhf[0], bhf[1], bhf[2], bhf[3], sb + K2_BH + xLane + ks);
            ldm_x4(bhf[4], bhf[5], bhf[6], bhf[7], sb + K2_BH + xLane + ks + 16 * STRB);
            ldm_x4(blf[0], blf[1], blf[2], blf[3], sb + K2_BL + xLane + ks);
            ldm_x4(blf[4], blf[5], blf[6], blf[7], sb + K2_BL + xLane + ks + 16 * STRB);
#pragma unroll
            for (int m = 0; m < 2; m++) {
                uint32_t ah0, ah1, ah2, ah3, al0, al1, al2, al3;
                uint32_t ao = aLane + (uint32_t)(m * 16 * STRB) + ks;
                ldm_x4(ah0, ah1, ah2, ah3, sb + K2_AH + ao);
                ldm_x4(al0, al1, al2, al3, sb + K2_AL + ao);
#pragma unroll
                for (int n = 0; n < 4; n++) {
                    uint32_t i0 = (uint32_t)((n >> 1) * 4 + (n & 1) * 2);
                    mma16816(acc[m][n], ah0, ah1, ah2, ah3, bhf[i0], bhf[i0 + 1]);
                    mma16816(acc[m][n], ah0, ah1, ah2, ah3, blf[i0], blf[i0 + 1]);
                    mma16816(acc[m][n], al0, al1, al2, al3, bhf[i0], bhf[i0 + 1]);
                }
            }
        }
        __syncthreads();
    }

    // epilogue: T[b][c][hBase+gm][gn] fp32
    float* Tp = g_T + ((size_t)(b * NC + c)) * HH * DD;
#pragma unroll
    for (int m = 0; m < 2; m++) {
#pragma unroll
        for (int n = 0; n < 4; n++) {
            int gm = hBase + wm * 32 + m * 16 + (l >> 2);
            int gn = wn * 32 + n * 8 + (l & 3) * 2;
            *(float2*)(Tp + (size_t)gm * 64 + gn) =
                make_float2(acc[m][n][0], acc[m][n][1]);
            *(float2*)(Tp + (size_t)(gm + 8) * 64 + gn) =
                make_float2(acc[m][n][2], acc[m][n][3]);
        }
    }
}

// ---------------------------------------------------------------------------
// K3: exclusive prefix over chunks: S[b][c] = sum_{c'<c} T[b][c'], split bf16
// ---------------------------------------------------------------------------
__global__ void __launch_bounds__(256) k_prefix() {
    int b = blockIdx.y;
    int hd = blockIdx.x * 256 + threadIdx.x;   // 0..49151
    float run = 0.f;
#pragma unroll
    for (int c = 0; c < NC; c++) {
        size_t o = ((size_t)(b * NC + c)) * HH * DD + hd;
        __nv_bfloat16 hi = __float2bfloat16(run);
        g_Sh[o] = hi;
        g_Sl[o] = __float2bfloat16(run - __bfloat162float(hi));
        run += g_T[o];
    }
}

// ---------------------------------------------------------------------------
// K4: per (b, chunk, hT):  out[j,h] = bx[j,h] + E'_j·S_c[h] + sum_{i<j} P[j,i] X[i,h]
// Phase B: P = E'·F'^T (masked), split to smem. C1: E'@S^T. C2: P@Xt^T.
// ---------------------------------------------------------------------------
#define OFF_EH  0
#define OFF_EL  TILE
#define OFF_FH  (2 * TILE)
#define OFF_FL  (3 * TILE)
#define OFF_PH  (4 * TILE)
#define OFF_PL  (4 * TILE + PTILE)
#define OFF_SH  (4 * TILE + 2 * PTILE)
#define OFF_SL  (5 * TILE + 2 * PTILE)
#define OFF_X0H (6 * TILE + 2 * PTILE)
#define OFF_X0L (7 * TILE + 2 * PTILE)
#define K4_SMEM (8 * TILE + 2 * PTILE)   // 217088

__global__ void __launch_bounds__(256, 1) k_apply2(const float* __restrict__ bx,
                                                   float* __restrict__ out) {
    extern __shared__ char smem[];
    uint32_t sb = smem_u32(smem);
    int tid = threadIdx.x, wid = tid >> 5, l = tid & 31;
    int hT = blockIdx.x, c = blockIdx.y, b = blockIdx.z;
    int hBase = hT * 128, jBase = c * CC;
    int wm = wid & 1, wn = wid >> 1;   // warp tile 64(m) x 32(n)

    int fRow = tid >> 3, fCol = tid & 7;
    uint32_t fOff = (uint32_t)(fRow * STRB + fCol * 16);

    // G0: E' + F' tiles
    {
        size_t eBase = ((size_t)b * LL + jBase) * 64;
#pragma unroll
        for (int v = 0; v < 4; v++) {
            uint32_t so = fOff + (uint32_t)(v * 32 * STRB);
            size_t go = eBase + (size_t)(fRow + v * 32) * 64 - (size_t)fRow * 64 +
                        (size_t)fRow * 64 + fCol * 8;  // = eBase + (fRow+v*32)*64 + fCol*8
            go = eBase + (size_t)(fRow + v * 32) * 64 + fCol * 8;
            cp16(sb + OFF_EH + so, g_Eph + go);
            cp16(sb + OFF_EL + so, g_Epl + go);
            cp16(sb + OFF_FH + so, g_Fph + go);
            cp16(sb + OFF_FL + so, g_Fpl + go);
        }
        CP_COMMIT();
    }
    // G1: S tiles
    {
        size_t sBase = (((size_t)(b * NC + c)) * HH + hBase) * 64;
#pragma unroll
        for (int v = 0; v < 4; v++) {
            uint32_t so = fOff + (uint32_t)(v * 32 * STRB);
            size_t go = sBase + (size_t)(fRow + v * 32) * 64 + fCol * 8;
            cp16(sb + OFF_SH + so, g_Sh + go);
            cp16(sb + OFF_SL + so, g_Sl + go);
        }
        CP_COMMIT();
    }
    // G2: Xt sub0 tiles
    {
        size_t xBase = ((size_t)(b * HH + hBase)) * LL + jBase;
#pragma unroll
        for (int v = 0; v < 4; v++) {
            uint32_t so = fOff + (uint32_t)(v * 32 * STRB);
            size_t go = xBase + (size_t)(fRow + v * 32) * LL + fCol * 8;
            cp16(sb + OFF_X0H + so, g_Xh + go);
            cp16(sb + OFF_X0L + so, g_Xl + go);
        }
        CP_COMMIT();
    }

    uint32_t aLane  = (uint32_t)((wm * 64 + (l & 15)) * STRB + (l >> 4) * 16);
    uint32_t aLaneP = (uint32_t)((wm * 64 + (l & 15)) * STRP + (l >> 4) * 16);
    uint32_t xLane  = (uint32_t)((wn * 32 + (l & 7) + ((l >> 4) * 8)) * STRB +
                                 ((l >> 3) & 1) * 16);

    float acc[4][4][4];
#pragma unroll
    for (int m = 0; m < 4; m++)
#pragma unroll
        for (int n = 0; n < 4; n++)
#pragma unroll
            for (int k = 0; k < 4; k++) acc[m][n][k] = 0.f;

    // ---- Phase B: P = E' F'^T, masked (i<j), split -> smem ----
    CP_WAIT(2);          // G0 done
    __syncthreads();
    gemm4(acc, sb + OFF_EH + aLane, sb + OFF_EL + aLane,
          sb + OFF_FH + xLane, sb + OFF_FL + xLane, 16 * STRB);

    // store masked P (bf16 hi/lo) to smem
#pragma unroll
    for (int m = 0; m < 4; m++) {
#pragma unroll
        for (int n = 0; n < 4; n++) {
            int gm = wm * 64 + m * 16 + (l >> 2);
            int gn = wn * 32 + n * 8 + (l & 3) * 2;
            float v0 = (gn < gm) ? acc[m][n][0] : 0.f;
            float v1 = (gn + 1 < gm) ? acc[m][n][1] : 0.f;
            float v2 = (gn < gm + 8) ? acc[m][n][2] : 0.f;
            float v3 = (gn + 1 < gm + 8) ? acc[m][n][3] : 0.f;
            uint32_t hi, lo;
            split2pack(v0, v1, hi, lo);
            *(uint32_t*)(smem + OFF_PH + gm * STRP + gn * 2) = hi;
            *(uint32_t*)(smem + OFF_PL + gm * STRP + gn * 2) = lo;
            split2pack(v2, v3, hi, lo);
            *(uint32_t*)(smem + OFF_PH + (gm + 8) * STRP + gn * 2) = hi;
            *(uint32_t*)(smem + OFF_PL + (gm + 8) * STRP + gn * 2) = lo;
        }
    }

    // reset acc for output accumulation
#pragma unroll
    for (int m = 0; m < 4; m++)
#pragma unroll
        for (int n = 0; n < 4; n++)
#pragma unroll
            for (int k = 0; k < 4; k++) acc[m][n][k] = 0.f;

    // ---- Phase C1: acc += E' @ S^T ----
    CP_WAIT(1);          // G1 (S) done
    __syncthreads();     // also publishes P stores
    gemm4(acc, sb + OFF_EH + aLane, sb + OFF_EL + aLane,
          sb + OFF_SH + xLane, sb + OFF_SL + xLane, 16 * STRB);
    __syncthreads();     // E' dead; safe to overwrite with Xt sub1

    // G3: Xt sub1 into E' space
    {
        size_t xBase = ((size_t)(b * HH + hBase)) * LL + jBase + 64;
#pragma unroll
        for (int v = 0; v < 4; v++) {
            uint32_t so = fOff + (uint32_t)(v * 32 * STRB);
            size_t go = xBase + (size_t)(fRow + v * 32) * LL + fCol * 8;
            cp16(sb + OFF_EH + so, g_Xh + go);
            cp16(sb + OFF_EL + so, g_Xl + go);
        }
        CP_COMMIT();
    }

    // ---- Phase C2 sub0: acc += P[:,0:64] @ Xt0^T ----
    CP_WAIT(1);          // G2 (Xt0) done, G3 may pend
    __syncthreads();
    gemm4(acc, sb + OFF_PH + aLaneP, sb + OFF_PL + aLaneP,
          sb + OFF_X0H + xLane, sb + OFF_X0L + xLane, 16 * STRP);

    // ---- Phase C2 sub1: acc += P[:,64:128] @ Xt1^T ----
    CP_WAIT(0);
    __syncthreads();
    gemm4(acc, sb + OFF_PH + aLaneP + 128, sb + OFF_PL + aLaneP + 128,
          sb + OFF_EH + xLane, sb + OFF_EL + xLane, 16 * STRP);

    // ---- epilogue: out = bx + acc ----
#pragma unroll
    for (int m = 0; m < 4; m++) {
#pragma unroll
        for (int n = 0; n < 4; n++) {
            int gj = jBase + wm * 64 + m * 16 + (l >> 2);
            int gh = hBase + wn * 32 + n * 8 + (l & 3) * 2;
            size_t o0 = ((size_t)b * LL + gj) * HH + gh;
            size_t o1 = ((size_t)b * LL + gj + 8) * HH + gh;
            float2 x0 = *(const float2*)(bx + o0);
            float2 x1 = *(const float2*)(bx + o1);
            *(float2*)(out + o0) = make_float2(x0.x + acc[m][n][0], x0.y + acc[m][n][1]);
            *(float2*)(out + o1) = make_float2(x1.x + acc[m][n][2], x1.y + acc[m][n][3]);
        }
    }
}

// ---------------------------------------------------------------------------
extern "C" void kernel_launch(void* const* d_in, const int* in_sizes, int n_in,
                              void* d_out, int out_size) {
    const float* bert_x = nullptr;
    const void*  x      = nullptr;
    const float* ae     = nullptr;
    const float* w      = nullptr;
    for (int i = 0; i < n_in; i++) {
        switch (in_sizes[i]) {
            case 25165824: bert_x = (const float*)d_in[i]; break;
            case 32768:    x      = d_in[i];               break;
            case 1920000:  ae     = (const float*)d_in[i]; break;
            case 4096:     w      = (const float*)d_in[i]; break;
            default: break;
        }
    }
    float* out = (float*)d_out;

    cudaFuncSetAttribute(k_chunksum,
                         cudaFuncAttributeMaxDynamicSharedMemorySize, K2_SMEM);
    cudaFuncSetAttribute(k_apply2,
                         cudaFuncAttributeMaxDynamicSharedMemorySize, K4_SMEM);

    k_prep<<<(BB * LL) / 4, 256>>>(ae, x, w);
    k_xprep<<<dim3(LL / 32, HH / 32, BB), dim3(32, 8)>>>(bert_x);
    k_chunksum<<<dim3(HH / 128, NC, BB), 256, K2_SMEM>>>();
    k_prefix<<<dim3(HH * DD / 256, BB), 256>>>();
    k_apply2<<<dim3(HH / 128, NC, BB), 256, K4_SMEM>>>(bert_x, out);
}

// round 7
// speedup vs baseline: 4.3735x; 1.1103x over previous
#include <cuda_runtime.h>
#include <cuda_bf16.h>
#include <cstdint>

#define BB 16
#define LL 2048
#define HH 768
#define DD 64
#define VV 30000
#define CC 128               // chunk length
#define NC 16                // number of chunks

// ---------------------------------------------------------------------------
// Device-global scratch
// ---------------------------------------------------------------------------
__device__ __nv_bfloat16 g_Eph[(size_t)BB * LL * DD];   // E' hi  [b][l][d]
__device__ __nv_bfloat16 g_Epl[(size_t)BB * LL * DD];   // E' lo
__device__ __nv_bfloat16 g_Fph[(size_t)BB * LL * DD];   // F' hi  [b][l][d]
__device__ __nv_bfloat16 g_Fpl[(size_t)BB * LL * DD];   // F' lo
__device__ __nv_bfloat16 g_Fth[(size_t)BB * DD * LL];   // F' hi  [b][d][l]
__device__ __nv_bfloat16 g_Ftl[(size_t)BB * DD * LL];   // F' lo
__device__ __nv_bfloat16 g_Xh[(size_t)BB * HH * LL];    // X hi   [b][h][l]
__device__ __nv_bfloat16 g_Xl[(size_t)BB * HH * LL];    // X lo
__device__ float         g_T [(size_t)BB * NC * HH * DD];  // chunk sums fp32
__device__ __nv_bfloat16 g_Sh[(size_t)BB * NC * HH * DD];  // excl prefix hi
__device__ __nv_bfloat16 g_Sl[(size_t)BB * NC * HH * DD];  // excl prefix lo
__device__ __nv_bfloat16 g_Ph[(size_t)BB * NC * CC * CC];  // masked P hi [b][c][j][i]
__device__ __nv_bfloat16 g_Pl[(size_t)BB * NC * CC * CC];  // masked P lo

// ---------------------------------------------------------------------------
// helpers
// ---------------------------------------------------------------------------
__device__ __forceinline__ uint32_t smem_u32(const void* p) {
    uint32_t a;
    asm("{ .reg .u64 t; cvta.to.shared.u64 t, %1; cvt.u32.u64 %0, t; }"
        : "=r"(a) : "l"(p));
    return a;
}
__device__ __forceinline__ void ldm_x4(uint32_t& r0, uint32_t& r1, uint32_t& r2,
                                       uint32_t& r3, uint32_t addr) {
    asm volatile("ldmatrix.sync.aligned.m8n8.x4.shared.b16 {%0,%1,%2,%3}, [%4];"
                 : "=r"(r0), "=r"(r1), "=r"(r2), "=r"(r3) : "r"(addr));
}
__device__ __forceinline__ void mma16816(float* c, uint32_t a0, uint32_t a1,
                                         uint32_t a2, uint32_t a3, uint32_t b0,
                                         uint32_t b1) {
    asm volatile(
        "mma.sync.aligned.m16n8k16.row.col.f32.bf16.bf16.f32 "
        "{%0,%1,%2,%3}, {%4,%5,%6,%7}, {%8,%9}, {%0,%1,%2,%3};"
        : "+f"(c[0]), "+f"(c[1]), "+f"(c[2]), "+f"(c[3])
        : "r"(a0), "r"(a1), "r"(a2), "r"(a3), "r"(b0), "r"(b1));
}
__device__ __forceinline__ void cp16(uint32_t s, const void* g) {
    asm volatile("cp.async.cg.shared.global [%0], [%1], 16;" :: "r"(s), "l"(g));
}
#define CP_COMMIT()  asm volatile("cp.async.commit_group;" ::: "memory")
#define CP_WAIT(n)   asm volatile("cp.async.wait_group %0;" :: "n"(n) : "memory")

__device__ __forceinline__ void split2pack(float a, float b, uint32_t& hi,
                                           uint32_t& lo) {
    __nv_bfloat16 ha = __float2bfloat16(a), hb = __float2bfloat16(b);
    __nv_bfloat16 la = __float2bfloat16(a - __bfloat162float(ha));
    __nv_bfloat16 lb = __float2bfloat16(b - __bfloat162float(hb));
    hi = (uint32_t)__bfloat16_as_ushort(ha) |
         ((uint32_t)__bfloat16_as_ushort(hb) << 16);
    lo = (uint32_t)__bfloat16_as_ushort(la) |
         ((uint32_t)__bfloat16_as_ushort(lb) << 16);
}

#define STRB  144   // 128x64-bf16 tile row stride (bytes)
#define TILE  18432 // 128*144
#define STRP  272   // P tile (128x128 bf16) row stride
#define PTILE 34816 // 128*272

// 4 k16-steps GEMM on a 64-wide K slab. acc[4][4][4], warp tile 64x32.
__device__ __forceinline__ void gemm4(float (&acc)[4][4][4], uint32_t aH,
                                      uint32_t aL, uint32_t bH, uint32_t bL,
                                      uint32_t aMstr) {
#pragma unroll
    for (int s = 0; s < 4; s++) {
        uint32_t ks = (uint32_t)(s * 32);
        uint32_t bhf[8], blf[8];
        ldm_x4(bhf[0], bhf[1], bhf[2], bhf[3], bH + ks);
        ldm_x4(bhf[4], bhf[5], bhf[6], bhf[7], bH + ks + 16 * STRB);
        ldm_x4(blf[0], blf[1], blf[2], blf[3], bL + ks);
        ldm_x4(blf[4], blf[5], blf[6], blf[7], bL + ks + 16 * STRB);
#pragma unroll
        for (int m = 0; m < 4; m++) {
            uint32_t ah0, ah1, ah2, ah3, al0, al1, al2, al3;
            ldm_x4(ah0, ah1, ah2, ah3, aH + m * aMstr + ks);
            ldm_x4(al0, al1, al2, al3, aL + m * aMstr + ks);
#pragma unroll
            for (int n = 0; n < 4; n++) {
                uint32_t i0 = (uint32_t)((n >> 1) * 4 + (n & 1) * 2);
                mma16816(acc[m][n], ah0, ah1, ah2, ah3, bhf[i0], bhf[i0 + 1]);
                mma16816(acc[m][n], ah0, ah1, ah2, ah3, blf[i0], blf[i0 + 1]);
                mma16816(acc[m][n], al0, al1, al2, al3, bhf[i0], bhf[i0 + 1]);
            }
        }
    }
}

// ---------------------------------------------------------------------------
// K1: E=ae[x], F=E@w; E'=E/(l+1), F'=F*(l+1); split+store.
// 64 rows per CTA (w loaded once) -> grid 512.
// ---------------------------------------------------------------------------
__global__ void __launch_bounds__(256) k_prep(const float* __restrict__ ae,
                                              const void* __restrict__ xraw,
                                              const float* __restrict__ w) {
    __shared__ float ws[64 * 64];
    __shared__ float es[4][64];
    for (int t = threadIdx.x; t < 64 * 64; t += 256) ws[t] = w[t];

    const int* xi = (const int*)xraw;
    bool is64 = true;
#pragma unroll
    for (int k = 0; k < 32; k++)
        if (xi[2 * k + 1] != 0) is64 = false;

    int sub = threadIdx.x >> 6;
    int d   = threadIdx.x & 63;

    for (int it = 0; it < 16; it++) {
        int row = blockIdx.x * 64 + it * 4 + sub;
        int b   = row >> 11, l = row & (LL - 1);

        long long tok;
        if (is64) tok = ((const long long*)xraw)[row];
        else      tok = (long long)xi[row];
        if (tok < 0) tok = 0;
        if (tok >= VV) tok = VV - 1;

        float e = ae[(size_t)tok * 64 + d];
        __syncthreads();
        es[sub][d] = e;
        __syncthreads();
        float f = 0.f;
#pragma unroll
        for (int k = 0; k < 64; k++) f += es[sub][k] * ws[k * 64 + d];

        float sc = (float)(l + 1);
        float ep = e / sc;
        float fp = f * sc;

        __nv_bfloat16 eh = __float2bfloat16(ep);
        __nv_bfloat16 el = __float2bfloat16(ep - __bfloat162float(eh));
        __nv_bfloat16 fh = __float2bfloat16(fp);
        __nv_bfloat16 fl = __float2bfloat16(fp - __bfloat162float(fh));

        size_t ro = (size_t)row * 64 + d;
        g_Eph[ro] = eh; g_Epl[ro] = el;
        g_Fph[ro] = fh; g_Fpl[ro] = fl;
        size_t to = ((size_t)b * 64 + d) * LL + l;
        g_Fth[to] = fh; g_Ftl[to] = fl;
    }
}

// ---------------------------------------------------------------------------
// K1b: transpose+split bert_x -> Xt[b][h][l] bf16 hi/lo
// ---------------------------------------------------------------------------
__global__ void __launch_bounds__(256) k_xprep(const float* __restrict__ bx) {
    __shared__ float t[32][33];
    int i0 = blockIdx.x * 32, h0 = blockIdx.y * 32, b = blockIdx.z;
    for (int r = threadIdx.y; r < 32; r += 8)
        t[r][threadIdx.x] = bx[((size_t)b * LL + i0 + r) * HH + h0 + threadIdx.x];
    __syncthreads();
    for (int r = threadIdx.y; r < 32; r += 8) {
        float v = t[threadIdx.x][r];
        __nv_bfloat16 hi = __float2bfloat16(v);
        size_t off = ((size_t)b * HH + h0 + r) * LL + i0 + threadIdx.x;
        g_Xh[off] = hi;
        g_Xl[off] = __float2bfloat16(v - __bfloat162float(hi));
    }
}

// ---------------------------------------------------------------------------
// K2: chunk sums  T[b][c][h][d] = sum_{i in chunk} X[i,h] * F'[i,d]
// ---------------------------------------------------------------------------
#define K2_AH 0
#define K2_AL TILE
#define K2_BH (2 * TILE)
#define K2_BL (2 * TILE + 9216)
#define K2_SMEM (2 * TILE + 2 * 9216)

__global__ void __launch_bounds__(256) k_chunksum() {
    extern __shared__ char smem[];
    uint32_t sb = smem_u32(smem);
    int tid = threadIdx.x, wid = tid >> 5, l = tid & 31;
    int hT = blockIdx.x, c = blockIdx.y, b = blockIdx.z;
    int hBase = hT * 128;
    int wm = wid & 3, wn = wid >> 2;

    float acc[2][4][4];
#pragma unroll
    for (int m = 0; m < 2; m++)
#pragma unroll
        for (int n = 0; n < 4; n++)
#pragma unroll
            for (int k = 0; k < 4; k++) acc[m][n][k] = 0.f;

    uint32_t aLane = (uint32_t)((wm * 32 + (l & 15)) * STRB + (l >> 4) * 16);
    uint32_t xLane = (uint32_t)((wn * 32 + (l & 7) + ((l >> 4) * 8)) * STRB +
                                ((l >> 3) & 1) * 16);

    for (int subk = 0; subk < 2; subk++) {
        size_t kOff = (size_t)c * CC + subk * 64;
#pragma unroll
        for (int v = 0; v < 4; v++) {
            int idx = v * 256 + tid;
            int row = idx >> 3, col = idx & 7;
            uint32_t so = (uint32_t)(row * STRB + col * 16);
            size_t go = ((size_t)(b * HH + hBase + row)) * LL + kOff + col * 8;
            cp16(sb + K2_AH + so, g_Xh + go);
            cp16(sb + K2_AL + so, g_Xl + go);
        }
#pragma unroll
        for (int v = 0; v < 2; v++) {
            int idx = v * 256 + tid;
            int row = idx >> 3, col = idx & 7;
            uint32_t so = (uint32_t)(row * STRB + col * 16);
            size_t go = ((size_t)(b * DD + row)) * LL + kOff + col * 8;
            cp16(sb + K2_BH + so, g_Fth + go);
            cp16(sb + K2_BL + so, g_Ftl + go);
        }
        CP_COMMIT();
        CP_WAIT(0);
        __syncthreads();

#pragma unroll
        for (int s = 0; s < 4; s++) {
            uint32_t ks = (uint32_t)(s * 32);
            uint32_t bhf[8], blf[8];
            ldm_x4(bhf[0], bhf[1], bhf[2], bhf[3], sb + K2_BH + xLane + ks);
            ldm_x4(bhf[4], bhf[5], bhf[6], bhf[7], sb + K2_BH + xLane + ks + 16 * STRB);
            ldm_x4(blf[0], blf[1], blf[2], blf[3], sb + K2_BL + xLane + ks);
            ldm_x4(blf[4], blf[5], blf[6], blf[7], sb + K2_BL + xLane + ks + 16 * STRB);
#pragma unroll
            for (int m = 0; m < 2; m++) {
                uint32_t ah0, ah1, ah2, ah3, al0, al1, al2, al3;
                uint32_t ao = aLane + (uint32_t)(m * 16 * STRB) + ks;
                ldm_x4(ah0, ah1, ah2, ah3, sb + K2_AH + ao);
                ldm_x4(al0, al1, al2, al3, sb + K2_AL + ao);
#pragma unroll
                for (int n = 0; n < 4; n++) {
                    uint32_t i0 = (uint32_t)((n >> 1) * 4 + (n & 1) * 2);
                    mma16816(acc[m][n], ah0, ah1, ah2, ah3, bhf[i0], bhf[i0 + 1]);
                    mma16816(acc[m][n], ah0, ah1, ah2, ah3, blf[i0], blf[i0 + 1]);
                    mma16816(acc[m][n], al0, al1, al2, al3, bhf[i0], bhf[i0 + 1]);
                }
            }
        }
        __syncthreads();
    }

    float* Tp = g_T + ((size_t)(b * NC + c)) * HH * DD;
#pragma unroll
    for (int m = 0; m < 2; m++) {
#pragma unroll
        for (int n = 0; n < 4; n++) {
            int gm = hBase + wm * 32 + m * 16 + (l >> 2);
            int gn = wn * 32 + n * 8 + (l & 3) * 2;
            *(float2*)(Tp + (size_t)gm * 64 + gn) =
                make_float2(acc[m][n][0], acc[m][n][1]);
            *(float2*)(Tp + (size_t)(gm + 8) * 64 + gn) =
                make_float2(acc[m][n][2], acc[m][n][3]);
        }
    }
}

// ---------------------------------------------------------------------------
// K3: exclusive prefix over chunks
// ---------------------------------------------------------------------------
__global__ void __launch_bounds__(256) k_prefix() {
    int b = blockIdx.y;
    int hd = blockIdx.x * 256 + threadIdx.x;
    float run = 0.f;
#pragma unroll
    for (int c = 0; c < NC; c++) {
        size_t o = ((size_t)(b * NC + c)) * HH * DD + hd;
        __nv_bfloat16 hi = __float2bfloat16(run);
        g_Sh[o] = hi;
        g_Sl[o] = __float2bfloat16(run - __bfloat162float(hi));
        run += g_T[o];
    }
}

// ---------------------------------------------------------------------------
// K3b: P[b][c][j][i] = (E'_j . F'_i) masked (i<j), split bf16 -> global.
// Computed ONCE per (b,c) (was 6x inside old apply).
// ---------------------------------------------------------------------------
#define PG_SMEM (4 * TILE)

__global__ void __launch_bounds__(256) k_pgen() {
    extern __shared__ char smem[];
    uint32_t sb = smem_u32(smem);
    int tid = threadIdx.x, wid = tid >> 5, l = tid & 31;
    int c = blockIdx.x, b = blockIdx.y;
    int jBase = c * CC;
    int wm = wid & 1, wn = wid >> 1;
    int fRow = tid >> 3, fCol = tid & 7;
    uint32_t fOff = (uint32_t)(fRow * STRB + fCol * 16);

    size_t eBase = ((size_t)b * LL + jBase) * 64;
#pragma unroll
    for (int v = 0; v < 4; v++) {
        uint32_t so = fOff + (uint32_t)(v * 32 * STRB);
        size_t go = eBase + (size_t)(fRow + v * 32) * 64 + fCol * 8;
        cp16(sb + 0 * TILE + so, g_Eph + go);
        cp16(sb + 1 * TILE + so, g_Epl + go);
        cp16(sb + 2 * TILE + so, g_Fph + go);
        cp16(sb + 3 * TILE + so, g_Fpl + go);
    }
    CP_COMMIT();
    CP_WAIT(0);
    __syncthreads();

    uint32_t aLane = (uint32_t)((wm * 64 + (l & 15)) * STRB + (l >> 4) * 16);
    uint32_t xLane = (uint32_t)((wn * 32 + (l & 7) + ((l >> 4) * 8)) * STRB +
                                ((l >> 3) & 1) * 16);

    float acc[4][4][4];
#pragma unroll
    for (int m = 0; m < 4; m++)
#pragma unroll
        for (int n = 0; n < 4; n++)
#pragma unroll
            for (int k = 0; k < 4; k++) acc[m][n][k] = 0.f;

    gemm4(acc, sb + 0 * TILE + aLane, sb + 1 * TILE + aLane,
          sb + 2 * TILE + xLane, sb + 3 * TILE + xLane, 16 * STRB);

    __nv_bfloat16* Ph = g_Ph + ((size_t)(b * NC + c)) * CC * CC;
    __nv_bfloat16* Pl = g_Pl + ((size_t)(b * NC + c)) * CC * CC;
#pragma unroll
    for (int m = 0; m < 4; m++) {
#pragma unroll
        for (int n = 0; n < 4; n++) {
            int gm = wm * 64 + m * 16 + (l >> 2);
            int gn = wn * 32 + n * 8 + (l & 3) * 2;
            float v0 = (gn < gm) ? acc[m][n][0] : 0.f;
            float v1 = (gn + 1 < gm) ? acc[m][n][1] : 0.f;
            float v2 = (gn < gm + 8) ? acc[m][n][2] : 0.f;
            float v3 = (gn + 1 < gm + 8) ? acc[m][n][3] : 0.f;
            uint32_t hi, lo;
            split2pack(v0, v1, hi, lo);
            *(uint32_t*)(Ph + (size_t)gm * CC + gn) = hi;
            *(uint32_t*)(Pl + (size_t)gm * CC + gn) = lo;
            split2pack(v2, v3, hi, lo);
            *(uint32_t*)(Ph + (size_t)(gm + 8) * CC + gn) = hi;
            *(uint32_t*)(Pl + (size_t)(gm + 8) * CC + gn) = lo;
        }
    }
}

// ---------------------------------------------------------------------------
// K4: out[j,h] = bx[j,h] + E'_j·S_c[h] + sum_{i<j} P[j,i] X[i,h]
// 3 GEMM phases (C1: E'@S^T, C2a: P0@X0^T, C2b: P1@X1^T), all prefetched.
// ---------------------------------------------------------------------------
#define OFF_EH  0
#define OFF_EL  TILE
#define OFF_SH  (2 * TILE)
#define OFF_SL  (3 * TILE)
#define OFF_X0H (4 * TILE)
#define OFF_X0L (5 * TILE)
#define OFF_PH  (6 * TILE)
#define OFF_PL  (6 * TILE + PTILE)
#define K4_SMEM (6 * TILE + 2 * PTILE)   // 180224

__global__ void __launch_bounds__(256, 1) k_apply2(const float* __restrict__ bx,
                                                   float* __restrict__ out) {
    extern __shared__ char smem[];
    uint32_t sb = smem_u32(smem);
    int tid = threadIdx.x, wid = tid >> 5, l = tid & 31;
    int hT = blockIdx.x, c = blockIdx.y, b = blockIdx.z;
    int hBase = hT * 128, jBase = c * CC;
    int wm = wid & 1, wn = wid >> 1;

    int fRow = tid >> 3, fCol = tid & 7;
    uint32_t fOff = (uint32_t)(fRow * STRB + fCol * 16);

    // G0: E' + S
    {
        size_t eBase = ((size_t)b * LL + jBase) * 64;
        size_t sBase = (((size_t)(b * NC + c)) * HH + hBase) * 64;
#pragma unroll
        for (int v = 0; v < 4; v++) {
            uint32_t so = fOff + (uint32_t)(v * 32 * STRB);
            size_t ge = eBase + (size_t)(fRow + v * 32) * 64 + fCol * 8;
            size_t gs = sBase + (size_t)(fRow + v * 32) * 64 + fCol * 8;
            cp16(sb + OFF_EH + so, g_Eph + ge);
            cp16(sb + OFF_EL + so, g_Epl + ge);
            cp16(sb + OFF_SH + so, g_Sh + gs);
            cp16(sb + OFF_SL + so, g_Sl + gs);
        }
        CP_COMMIT();
    }
    // G1: Xt sub0
    {
        size_t xBase = ((size_t)(b * HH + hBase)) * LL + jBase;
#pragma unroll
        for (int v = 0; v < 4; v++) {
            uint32_t so = fOff + (uint32_t)(v * 32 * STRB);
            size_t go = xBase + (size_t)(fRow + v * 32) * LL + fCol * 8;
            cp16(sb + OFF_X0H + so, g_Xh + go);
            cp16(sb + OFF_X0L + so, g_Xl + go);
        }
        CP_COMMIT();
    }
    // G2: P (hi/lo), 128 rows x 16 16B-cols each
    {
        const __nv_bfloat16* Ph = g_Ph + ((size_t)(b * NC + c)) * CC * CC;
        const __nv_bfloat16* Pl = g_Pl + ((size_t)(b * NC + c)) * CC * CC;
#pragma unroll
        for (int v = 0; v < 8; v++) {
            int idx = v * 256 + tid;
            int row = idx >> 4, col = idx & 15;
            uint32_t so = (uint32_t)(row * STRP + col * 16);
            size_t go = (size_t)row * CC + col * 8;
            cp16(sb + OFF_PH + so, Ph + go);
            cp16(sb + OFF_PL + so, Pl + go);
        }
        CP_COMMIT();
    }

    uint32_t aLane  = (uint32_t)((wm * 64 + (l & 15)) * STRB + (l >> 4) * 16);
    uint32_t aLaneP = (uint32_t)((wm * 64 + (l & 15)) * STRP + (l >> 4) * 16);
    uint32_t xLane  = (uint32_t)((wn * 32 + (l & 7) + ((l >> 4) * 8)) * STRB +
                                 ((l >> 3) & 1) * 16);

    float acc[4][4][4];
#pragma unroll
    for (int m = 0; m < 4; m++)
#pragma unroll
        for (int n = 0; n < 4; n++)
#pragma unroll
            for (int k = 0; k < 4; k++) acc[m][n][k] = 0.f;

    // ---- C1: acc += E' @ S^T ----
    CP_WAIT(2);
    __syncthreads();
    gemm4(acc, sb + OFF_EH + aLane, sb + OFF_EL + aLane,
          sb + OFF_SH + xLane, sb + OFF_SL + xLane, 16 * STRB);
    __syncthreads();   // E' dead; reuse for Xt sub1

    // G3: Xt sub1 into E' space
    {
        size_t xBase = ((size_t)(b * HH + hBase)) * LL + jBase + 64;
#pragma unroll
        for (int v = 0; v < 4; v++) {
            uint32_t so = fOff + (uint32_t)(v * 32 * STRB);
            size_t go = xBase + (size_t)(fRow + v * 32) * LL + fCol * 8;
            cp16(sb + OFF_EH + so, g_Xh + go);
            cp16(sb + OFF_EL + so, g_Xl + go);
        }
        CP_COMMIT();
    }

    // ---- C2a: acc += P[:,0:64] @ X0^T ----
    CP_WAIT(1);        // G1 + G2 done (only G3 may pend)
    __syncthreads();
    gemm4(acc, sb + OFF_PH + aLaneP, sb + OFF_PL + aLaneP,
          sb + OFF_X0H + xLane, sb + OFF_X0L + xLane, 16 * STRP);

    // ---- C2b: acc += P[:,64:128] @ X1^T ----
    CP_WAIT(0);
    __syncthreads();
    gemm4(acc, sb + OFF_PH + aLaneP + 128, sb + OFF_PL + aLaneP + 128,
          sb + OFF_EH + xLane, sb + OFF_EL + xLane, 16 * STRP);

    // ---- epilogue ----
#pragma unroll
    for (int m = 0; m < 4; m++) {
#pragma unroll
        for (int n = 0; n < 4; n++) {
            int gj = jBase + wm * 64 + m * 16 + (l >> 2);
            int gh = hBase + wn * 32 + n * 8 + (l & 3) * 2;
            size_t o0 = ((size_t)b * LL + gj) * HH + gh;
            size_t o1 = ((size_t)b * LL + gj + 8) * HH + gh;
            float2 x0 = *(const float2*)(bx + o0);
            float2 x1 = *(const float2*)(bx + o1);
            *(float2*)(out + o0) = make_float2(x0.x + acc[m][n][0], x0.y + acc[m][n][1]);
            *(float2*)(out + o1) = make_float2(x1.x + acc[m][n][2], x1.y + acc[m][n][3]);
        }
    }
}

// ---------------------------------------------------------------------------
extern "C" void kernel_launch(void* const* d_in, const int* in_sizes, int n_in,
                              void* d_out, int out_size) {
    const float* bert_x = nullptr;
    const void*  x      = nullptr;
    const float* ae     = nullptr;
    const float* w      = nullptr;
    for (int i = 0; i < n_in; i++) {
        switch (in_sizes[i]) {
            case 25165824: bert_x = (const float*)d_in[i]; break;
            case 32768:    x      = d_in[i];               break;
            case 1920000:  ae     = (const float*)d_in[i]; break;
            case 4096:     w      = (const float*)d_in[i]; break;
            default: break;
        }
    }
    float* out = (float*)d_out;

    cudaFuncSetAttribute(k_chunksum,
                         cudaFuncAttributeMaxDynamicSharedMemorySize, K2_SMEM);
    cudaFuncSetAttribute(k_pgen,
                         cudaFuncAttributeMaxDynamicSharedMemorySize, PG_SMEM);
    cudaFuncSetAttribute(k_apply2,
                         cudaFuncAttributeMaxDynamicSharedMemorySize, K4_SMEM);

    k_prep<<<512, 256>>>(ae, x, w);
    k_xprep<<<dim3(LL / 32, HH / 32, BB), dim3(32, 8)>>>(bert_x);
    k_pgen<<<dim3(NC, BB), 256, PG_SMEM>>>();
    k_chunksum<<<dim3(HH / 128, NC, BB), 256, K2_SMEM>>>();
    k_prefix<<<dim3(HH * DD / 256, BB), 256>>>();
    k_apply2<<<dim3(HH / 128, NC, BB), 256, K4_SMEM>>>(bert_x, out);
}